// round 2
// baseline (speedup 1.0000x reference)
#include <cuda_runtime.h>

// Reference collapse:
//   preds = softmax(logits + g, axis=-1) with PRED_BITS == 1  =>  preds == 1.0 exactly
//   (softmax over a length-1 axis of any finite value is 1.0; all inputs finite).
// Therefore each branch output is:
//   out[b, j, 0] = 1.0 if (b, j) in zip(tuple_state, within_idx) else 0.0
// and all three branches are identical. The conv/FC pipeline is dead code.
//
// Inputs (metadata order):
//   0 state, 1 state_next, 2 state_tilda, 3 gnoise, 4 gnoise_next, 5 gnoise_tilda,
//   6 conv_w, 7 conv_b, 8 fc2_w, 9 fc2_b, 10 fc3_w, 11 fc3_b,
//   12 tuple_state, 13 tuple_a, 14 tuple_b, 15 within_idx, 16 temp
//
// Output: 3 branches concatenated, each B*NMAX^2*P = 32*64*1 = 2048 float32.

__global__ void fosae_scatter_ones(const int* __restrict__ tuple_state,
                                   const int* __restrict__ within_idx,
                                   int T,
                                   float* __restrict__ out,
                                   int per_branch)
{
    const int tid = threadIdx.x;
    const int total = 3 * per_branch;

    // Zero the whole output (single block -> __syncthreads gives ordering).
    for (int j = tid; j < total; j += blockDim.x) {
        out[j] = 0.0f;
    }
    __syncthreads();

    // Scatter 1.0 into each branch. Targets are unique per t (state, within_idx)
    // pairs are distinct, so no write conflicts among scatter threads.
    for (int t = tid; t < T; t += blockDim.x) {
        const int pos = tuple_state[t] * 64 + within_idx[t];  // NMAX^2 * P = 64
        out[pos]                  = 1.0f;
        out[per_branch + pos]     = 1.0f;
        out[2 * per_branch + pos] = 1.0f;
    }
}

extern "C" void kernel_launch(void* const* d_in, const int* in_sizes, int n_in,
                              void* d_out, int out_size)
{
    const int* tuple_state = (const int*)d_in[12];
    const int* within_idx  = (const int*)d_in[15];
    const int  T           = in_sizes[12];

    float* out = (float*)d_out;
    const int per_branch = out_size / 3;  // B * NMAX^2 * P

    fosae_scatter_ones<<<1, 256>>>(tuple_state, within_idx, T, out, per_branch);
}